// round 12
// baseline (speedup 1.0000x reference)
#include <cuda_runtime.h>
#include <cuda_fp16.h>
#include <stdint.h>
#include <math.h>

#define DF 512
#define MAXN 100000
#define MAXE 3200000

// ---------------- device scratch (no dynamic allocation allowed) -------------
__device__ __half g_x16[(size_t)MAXN * DF];    // fp16 x
__device__ __half g_w16t[3 * DF * DF];         // fp16, TRANSPOSED [z][n][k]
__device__ __half g_support_h[(size_t)MAXN * DF];
__device__ float  g_trans[(size_t)MAXN * DF];
__device__ __half g_gate_h[(size_t)MAXN * DF];
__device__ int    g_row_cnt[MAXN];
__device__ int    g_row_start[MAXN];
__device__ int    g_row_cur[MAXN];
__device__ int    g_partials[256];
__device__ int2   g_edges[MAXE];   // (col, val-as-bits) grouped by row

// ---------------- helpers ----------------------------------------------------
__device__ __forceinline__ void mma_f16(float c[4], const unsigned a[4], const unsigned b[2]) {
    asm volatile(
        "mma.sync.aligned.m16n8k16.row.col.f32.f16.f16.f32 "
        "{%0,%1,%2,%3}, {%4,%5,%6,%7}, {%8,%9}, {%0,%1,%2,%3};"
        : "+f"(c[0]), "+f"(c[1]), "+f"(c[2]), "+f"(c[3])
        : "r"(a[0]), "r"(a[1]), "r"(a[2]), "r"(a[3]), "r"(b[0]), "r"(b[1]));
}

__device__ __forceinline__ void ldsm_x4(unsigned& r0, unsigned& r1, unsigned& r2, unsigned& r3,
                                        uint32_t addr) {
    asm volatile("ldmatrix.sync.aligned.m8n8.x4.shared.b16 {%0,%1,%2,%3}, [%4];"
                 : "=r"(r0), "=r"(r1), "=r"(r2), "=r"(r3) : "r"(addr));
}

__device__ __forceinline__ void cp16(unsigned int dst, const void* src, bool valid) {
    int sz = valid ? 16 : 0;
    asm volatile("cp.async.cg.shared.global [%0], [%1], 16, %2;"
                 :: "r"(dst), "l"(src), "r"(sz));
}
__device__ __forceinline__ void cp_commit() { asm volatile("cp.async.commit_group;" ::: "memory"); }
__device__ __forceinline__ void cp_wait1()  { asm volatile("cp.async.wait_group 1;" ::: "memory"); }

__device__ __forceinline__ float sigmoidf_fast(float v) { return 1.0f / (1.0f + __expf(-v)); }

__device__ __forceinline__ uint32_t smem_u32(const void* p) {
    uint32_t a;
    asm("{ .reg .u64 t; cvta.to.shared.u64 t, %1; cvt.u32.u64 %0, t; }" : "=r"(a) : "l"(p));
    return a;
}

__device__ __forceinline__ unsigned h2_bits(__half2 h) {
    unsigned u;
    *reinterpret_cast<__half2*>(&u) = h;
    return u;
}

// ---------------- fp16 pre-conversion passes ----------------------------------
__global__ __launch_bounds__(256) void cvt_x_kernel(const float* __restrict__ x, int total4) {
    for (int i = blockIdx.x * blockDim.x + threadIdx.x; i < total4; i += gridDim.x * blockDim.x) {
        const float4 v = __ldcs(reinterpret_cast<const float4*>(x) + i);
        uint2 o;
        o.x = h2_bits(__floats2half2_rn(v.x, v.y));
        o.y = h2_bits(__floats2half2_rn(v.z, v.w));
        reinterpret_cast<uint2*>(g_x16)[i] = o;
    }
}

// fp16 + transpose: g_w16t[z][n][k] = h(w_z[k][n])
__global__ __launch_bounds__(256) void cvt_wt_kernel(
    const float* __restrict__ w1, const float* __restrict__ w2, const float* __restrict__ w3) {
    __shared__ float tile[32][33];
    const int z = blockIdx.z;
    const float* __restrict__ w = (z == 0) ? w1 : ((z == 1) ? w2 : w3);
    const int n0 = blockIdx.x * 32;
    const int k0 = blockIdx.y * 32;
    const int tx = threadIdx.x & 31;
    const int ty = threadIdx.x >> 5;   // 0..7
#pragma unroll
    for (int i = 0; i < 32; i += 8)
        tile[ty + i][tx] = w[(size_t)(k0 + ty + i) * DF + n0 + tx];
    __syncthreads();
#pragma unroll
    for (int i = 0; i < 32; i += 8)
        g_w16t[(size_t)z * DF * DF + (size_t)(n0 + ty + i) * DF + k0 + tx] =
            __float2half_rn(tile[tx][ty + i]);
}

// ---------------- fused triple GEMM (fp16 m16n8k16 + ldmatrix) ----------------
// Block tile 256(M) x 128(N), K-tile 64, double-buffered dynamic smem (96KB).
// 512 threads = 16 warps (8 M x 2 N), warp tile 32x64 = 2x8 m16n8k16 fragments.
// grid.x = 12 combos (4 bn x 3 z) -> consecutive CTAs share the A tile in L2.
// Doubling M per CTA doubles MMA work per LDS byte -> tensor-pipe bound.
#define ROWB 144                        // bytes per smem row (72 halves, conflict-free)
#define A_TILE_BYTES (256 * ROWB)       // 36864
#define B_TILE_BYTES (128 * ROWB)       // 18432
#define STAGE_BYTES (A_TILE_BYTES + B_TILE_BYTES)
#define GEMM_SMEM (2 * STAGE_BYTES)     // 110592

__global__ __launch_bounds__(512, 1) void gemm3_kernel(
    const float* __restrict__ b2, const float* __restrict__ b3, int n)
{
    extern __shared__ __half smh[];
    const uint32_t smem_base = smem_u32(smh);

    const int combo = blockIdx.x;       // 0..11
    const int bn = (combo & 3) * 128;
    const int z  = combo >> 2;          // 0..2
    const int bm = blockIdx.y * 256;
    const __half* __restrict__ wz = g_w16t + (size_t)z * DF * DF;

    const int t    = threadIdx.x;
    const int lane = t & 31;
    const int warp = t >> 5;            // 0..15
    const int wm   = (warp & 7) * 32;   // 8 M-groups
    const int wn   = (warp >> 3) * 64;  // 2 N-groups
    const int gid  = lane >> 2;
    const int tig  = lane & 3;

    float acc[2][8][4];
#pragma unroll
    for (int mi = 0; mi < 2; mi++)
#pragma unroll
        for (int ni = 0; ni < 8; ni++)
#pragma unroll
            for (int r = 0; r < 4; r++) acc[mi][ni][r] = 0.0f;

    // ldmatrix per-lane address offsets (bytes, within a tile)
    const uint32_t aoff = (uint32_t)((wm + (lane & 15)) * ROWB + (lane >> 4) * 16);
    const uint32_t boff = (uint32_t)((wn + (lane & 7) + ((lane & 16) ? 8 : 0)) * ROWB
                                     + ((lane >> 3) & 1) * 16);

    const int NT = DF / 64;   // 8 k-tiles

    // fill: A 256x64 halves = 2048 16B-chunks (4/thread), B 128x64 = 1024 (2/thread)
#define DO_PREFETCH(BF, K0)                                                          \
    {                                                                                \
        const uint32_t ab_ = smem_base + (BF) * STAGE_BYTES;                         \
        const uint32_t bb_ = ab_ + A_TILE_BYTES;                                     \
        _Pragma("unroll")                                                            \
        for (int i = 0; i < 4; i++) {                                                \
            const int idx = t + i * 512;                                             \
            const int r_  = idx >> 3;                                                \
            const int ch_ = idx & 7;                                                 \
            cp16(ab_ + r_ * ROWB + ch_ * 16,                                         \
                 g_x16 + (size_t)(bm + r_) * DF + (K0) + ch_ * 8, (bm + r_) < n);    \
        }                                                                            \
        _Pragma("unroll")                                                            \
        for (int i = 0; i < 2; i++) {                                                \
            const int idx = t + i * 512;                                             \
            const int r_  = idx >> 3;                                                \
            const int ch_ = idx & 7;                                                 \
            cp16(bb_ + r_ * ROWB + ch_ * 16,                                         \
                 wz + (size_t)(bn + r_) * DF + (K0) + ch_ * 8, true);                \
        }                                                                            \
    }

    int cb = 0;
    DO_PREFETCH(0, 0)
    cp_commit();

    for (int kt = 0; kt < NT; kt++) {
        if (kt + 1 < NT) DO_PREFETCH(cb ^ 1, (kt + 1) * 64)
        cp_commit();
        cp_wait1();
        __syncthreads();

        const uint32_t abase = smem_base + cb * STAGE_BYTES;
        const uint32_t bbase = abase + A_TILE_BYTES;

#pragma unroll
        for (int kk = 0; kk < 4; kk++) {           // 4 x k16 per tile
            const uint32_t kb = (uint32_t)(kk * 32);   // 16 halves = 32 bytes
            unsigned a[2][4];
#pragma unroll
            for (int mi = 0; mi < 2; mi++)
                ldsm_x4(a[mi][0], a[mi][1], a[mi][2], a[mi][3],
                        abase + aoff + mi * (16 * ROWB) + kb);
            unsigned b[8][2];
#pragma unroll
            for (int p = 0; p < 4; p++)
                ldsm_x4(b[2 * p][0], b[2 * p][1], b[2 * p + 1][0], b[2 * p + 1][1],
                        bbase + boff + p * (16 * ROWB) + kb);
#pragma unroll
            for (int mi = 0; mi < 2; mi++)
#pragma unroll
                for (int ni = 0; ni < 8; ni++)
                    mma_f16(acc[mi][ni], a[mi], b[ni]);
        }
        __syncthreads();
        cb ^= 1;
    }
#undef DO_PREFETCH

    // epilogue
    const float* __restrict__ bias = (z == 1) ? b2 : b3;

#pragma unroll
    for (int mi = 0; mi < 2; mi++) {
#pragma unroll
        for (int ni = 0; ni < 8; ni++) {
            const int col = bn + wn + ni * 8 + tig * 2;
            const int r0  = bm + wm + mi * 16 + gid;
            float v0 = acc[mi][ni][0], v1 = acc[mi][ni][1];
            float v2 = acc[mi][ni][2], v3 = acc[mi][ni][3];
            if (z >= 1) {
                const float bb0 = bias[col], bb1 = bias[col + 1];
                v0 += bb0; v1 += bb1; v2 += bb0; v3 += bb1;
            }
            if (z == 2) {
                v0 = sigmoidf_fast(v0); v1 = sigmoidf_fast(v1);
                v2 = sigmoidf_fast(v2); v3 = sigmoidf_fast(v3);
            }
            if (z == 1) {
                if (r0 < n)
                    *(float2*)(g_trans + (size_t)r0 * DF + col) = make_float2(v0, v1);
                if (r0 + 8 < n)
                    *(float2*)(g_trans + (size_t)(r0 + 8) * DF + col) = make_float2(v2, v3);
            } else {
                __half* __restrict__ outp = (z == 0) ? g_support_h : g_gate_h;
                if (r0 < n)
                    *(__half2*)(outp + (size_t)r0 * DF + col) = __floats2half2_rn(v0, v1);
                if (r0 + 8 < n)
                    *(__half2*)(outp + (size_t)(r0 + 8) * DF + col) = __floats2half2_rn(v2, v3);
            }
        }
    }
}

// ---------------- CSR build --------------------------------------------------
__global__ void zero_cnt_kernel(int n) {
    const int i = blockIdx.x * blockDim.x + threadIdx.x;
    if (i < n) g_row_cnt[i] = 0;
}

__global__ void hist_kernel(const int* __restrict__ er, int E) {
    for (int i = blockIdx.x * blockDim.x + threadIdx.x; i < E; i += gridDim.x * blockDim.x)
        atomicAdd(&g_row_cnt[__ldg(er + i)], 1);
}

__global__ __launch_bounds__(256) void scan_reduce_kernel(int n) {
    __shared__ int s[256];
    const int b = blockIdx.x, t = threadIdx.x;
    const int i0 = b * 512 + t;
    const int i1 = i0 + 256;
    int v = 0;
    if (i0 < n) v += g_row_cnt[i0];
    if (i1 < n) v += g_row_cnt[i1];
    s[t] = v;
    __syncthreads();
#pragma unroll
    for (int off = 128; off > 0; off >>= 1) {
        if (t < off) s[t] += s[t + off];
        __syncthreads();
    }
    if (t == 0) g_partials[b] = s[0];
}

__global__ __launch_bounds__(256) void scan_offsets_kernel(int nb) {
    __shared__ int s[256];
    const int t = threadIdx.x;
    const int v = (t < nb) ? g_partials[t] : 0;
    s[t] = v;
    __syncthreads();
#pragma unroll
    for (int off = 1; off < 256; off <<= 1) {
        const int u = (t >= off) ? s[t - off] : 0;
        __syncthreads();
        s[t] += u;
        __syncthreads();
    }
    if (t < nb) g_partials[t] = s[t] - v;   // exclusive
}

__global__ __launch_bounds__(256) void scan_fill_kernel(int n) {
    __shared__ int s[256];
    const int b = blockIdx.x, t = threadIdx.x;
    const int i0 = b * 512 + 2 * t;
    const int c0 = (i0 < n)     ? g_row_cnt[i0]     : 0;
    const int c1 = (i0 + 1 < n) ? g_row_cnt[i0 + 1] : 0;
    s[t] = c0 + c1;
    __syncthreads();
#pragma unroll
    for (int off = 1; off < 256; off <<= 1) {
        const int u = (t >= off) ? s[t - off] : 0;
        __syncthreads();
        s[t] += u;
        __syncthreads();
    }
    const int excl = s[t] - (c0 + c1) + g_partials[b];
    if (i0 < n)     { g_row_start[i0]     = excl;      g_row_cur[i0]     = excl; }
    if (i0 + 1 < n) { g_row_start[i0 + 1] = excl + c0; g_row_cur[i0 + 1] = excl + c0; }
}

__global__ void scatter_kernel(const int* __restrict__ er, const int* __restrict__ ec,
                               const float* __restrict__ ev, int E) {
    for (int i = blockIdx.x * blockDim.x + threadIdx.x; i < E; i += gridDim.x * blockDim.x) {
        const int r = __ldcs(er + i);
        const int p = atomicAdd(&g_row_cur[r], 1);
        g_edges[p] = make_int2(__ldcs(ec + i), __float_as_int(__ldcs(ev + i)));
    }
}

// ---------------- aggregation + fused final epilogue -------------------------
__device__ __forceinline__ void fma8_h(float acc[8], const uint4 raw, const float val) {
    const float2 f0 = __half22float2(*reinterpret_cast<const __half2*>(&raw.x));
    const float2 f1 = __half22float2(*reinterpret_cast<const __half2*>(&raw.y));
    const float2 f2 = __half22float2(*reinterpret_cast<const __half2*>(&raw.z));
    const float2 f3 = __half22float2(*reinterpret_cast<const __half2*>(&raw.w));
    acc[0] = fmaf(val, f0.x, acc[0]); acc[1] = fmaf(val, f0.y, acc[1]);
    acc[2] = fmaf(val, f1.x, acc[2]); acc[3] = fmaf(val, f1.y, acc[3]);
    acc[4] = fmaf(val, f2.x, acc[4]); acc[5] = fmaf(val, f2.y, acc[5]);
    acc[6] = fmaf(val, f3.x, acc[6]); acc[7] = fmaf(val, f3.y, acc[7]);
}

__global__ __launch_bounds__(64) void aggregate_kernel(
    const float* __restrict__ b1, float* __restrict__ out, int n)
{
    const int row = blockIdx.x;
    const int t   = threadIdx.x;
    const int c   = t << 3;

    const int start = g_row_start[row];
    const int deg   = g_row_cnt[row];

    float acc[8];
#pragma unroll
    for (int i = 0; i < 8; i++) acc[i] = 0.0f;

    __shared__ int2 se[64];

    for (int base = 0; base < deg; base += 64) {
        const int m = min(64, deg - base);
        if (t < m) se[t] = g_edges[start + base + t];
        __syncthreads();

        int i = 0;
        for (; i + 4 <= m; i += 4) {
            const int2 e0 = se[i], e1 = se[i + 1], e2 = se[i + 2], e3 = se[i + 3];
            const uint4 r0 = *reinterpret_cast<const uint4*>(g_support_h + (size_t)e0.x * DF + c);
            const uint4 r1 = *reinterpret_cast<const uint4*>(g_support_h + (size_t)e1.x * DF + c);
            const uint4 r2 = *reinterpret_cast<const uint4*>(g_support_h + (size_t)e2.x * DF + c);
            const uint4 r3 = *reinterpret_cast<const uint4*>(g_support_h + (size_t)e3.x * DF + c);
            fma8_h(acc, r0, __int_as_float(e0.y));
            fma8_h(acc, r1, __int_as_float(e1.y));
            fma8_h(acc, r2, __int_as_float(e2.y));
            fma8_h(acc, r3, __int_as_float(e3.y));
        }
        for (; i < m; i++) {
            const int2 e = se[i];
            const uint4 r = *reinterpret_cast<const uint4*>(g_support_h + (size_t)e.x * DF + c);
            fma8_h(acc, r, __int_as_float(e.y));
        }
        __syncthreads();
    }

    const size_t off = (size_t)row * DF + c;
    const float4 bb0 = *(const float4*)(b1 + c);
    const float4 bb1 = *(const float4*)(b1 + c + 4);
    const float4 tr0 = *(const float4*)(g_trans + off);
    const float4 tr1 = *(const float4*)(g_trans + off + 4);
    const uint4 graw = *(const uint4*)(g_gate_h + off);   // 8 halves
    const float2 g0 = __half22float2(*reinterpret_cast<const __half2*>(&graw.x));
    const float2 g1 = __half22float2(*reinterpret_cast<const __half2*>(&graw.y));
    const float2 g2 = __half22float2(*reinterpret_cast<const __half2*>(&graw.z));
    const float2 g3 = __half22float2(*reinterpret_cast<const __half2*>(&graw.w));

    float4 o0, o1;
    float r;
    r = fmaxf(acc[0] + bb0.x, 0.f);  o0.x = tr0.x + g0.x * (r - tr0.x);
    r = fmaxf(acc[1] + bb0.y, 0.f);  o0.y = tr0.y + g0.y * (r - tr0.y);
    r = fmaxf(acc[2] + bb0.z, 0.f);  o0.z = tr0.z + g1.x * (r - tr0.z);
    r = fmaxf(acc[3] + bb0.w, 0.f);  o0.w = tr0.w + g1.y * (r - tr0.w);
    r = fmaxf(acc[4] + bb1.x, 0.f);  o1.x = tr1.x + g2.x * (r - tr1.x);
    r = fmaxf(acc[5] + bb1.y, 0.f);  o1.y = tr1.y + g2.y * (r - tr1.y);
    r = fmaxf(acc[6] + bb1.z, 0.f);  o1.z = tr1.z + g3.x * (r - tr1.z);
    r = fmaxf(acc[7] + bb1.w, 0.f);  o1.w = tr1.w + g3.y * (r - tr1.w);
    __stcs((float4*)(out + off), o0);
    __stcs((float4*)(out + off + 4), o1);
}

// ---------------- launch ------------------------------------------------------
extern "C" void kernel_launch(void* const* d_in, const int* in_sizes, int n_in,
                              void* d_out, int out_size)
{
    const float* x  = (const float*)d_in[0];
    const float* w1 = (const float*)d_in[1];
    const float* w2 = (const float*)d_in[2];
    const float* w3 = (const float*)d_in[3];
    const float* b1 = (const float*)d_in[4];
    const float* b2 = (const float*)d_in[5];
    const float* b3 = (const float*)d_in[6];
    const int*   er = (const int*)d_in[7];
    const int*   ec = (const int*)d_in[8];
    const float* ev = (const float*)d_in[9];

    const int n = in_sizes[0] / DF;   // 100000
    const int E = in_sizes[7];        // 3200000
    float* out = (float*)d_out;

    static bool attr_set = false;
    if (!attr_set) {
        cudaFuncSetAttribute(gemm3_kernel, cudaFuncAttributeMaxDynamicSharedMemorySize, GEMM_SMEM);
        attr_set = true;
    }

    // launches 1-3
    const int total4 = n * DF / 4;
    cvt_x_kernel<<<2048, 256>>>(x, total4);
    dim3 wtg(DF / 32, DF / 32, 3);
    cvt_wt_kernel<<<wtg, 256>>>(w1, w2, w3);
    zero_cnt_kernel<<<(n + 255) / 256, 256>>>(n);

    // launch 4 = fp16 GEMM (profiled slot)
    dim3 ggrid(12, (n + 255) / 256, 1);
    gemm3_kernel<<<ggrid, 512, GEMM_SMEM>>>(b2, b3, n);

    const int nb = (n + 511) / 512;   // <= 256
    hist_kernel<<<2048, 256>>>(er, E);
    scan_reduce_kernel<<<nb, 256>>>(n);
    scan_offsets_kernel<<<1, 256>>>(nb);
    scan_fill_kernel<<<nb, 256>>>(n);
    scatter_kernel<<<2048, 256>>>(er, ec, ev, E);

    aggregate_kernel<<<n, 64>>>(b1, out, n);
}

// round 13
// speedup vs baseline: 1.0997x; 1.0997x over previous
#include <cuda_runtime.h>
#include <cuda_fp16.h>
#include <stdint.h>
#include <math.h>

#define DF 512
#define MAXN 100000
#define MAXE 3200000

// ---------------- device scratch (no dynamic allocation allowed) -------------
__device__ __half g_x16[(size_t)MAXN * DF];    // fp16 x
__device__ __half g_w16t[3 * DF * DF];         // fp16, TRANSPOSED [z][n][k]
__device__ __half g_support_h[(size_t)MAXN * DF];
__device__ float  g_trans[(size_t)MAXN * DF];
__device__ __half g_gate_h[(size_t)MAXN * DF];
__device__ int    g_row_cnt[MAXN];
__device__ int    g_row_start[MAXN];
__device__ int    g_row_cur[MAXN];
__device__ int    g_partials[256];
__device__ int2   g_edges[MAXE];   // (col, val-as-bits) grouped by row

// ---------------- host-side static stream/events (created pre-checkpoint) ----
static cudaStream_t g_s1;
static cudaEvent_t  g_evFork, g_evJoin;
static bool g_res_init = []() {
    cudaStreamCreateWithFlags(&g_s1, cudaStreamNonBlocking);
    cudaEventCreateWithFlags(&g_evFork, cudaEventDisableTiming);
    cudaEventCreateWithFlags(&g_evJoin, cudaEventDisableTiming);
    return true;
}();

// ---------------- helpers ----------------------------------------------------
__device__ __forceinline__ void mma_f16(float c[4], const unsigned a[4], const unsigned b[2]) {
    asm volatile(
        "mma.sync.aligned.m16n8k16.row.col.f32.f16.f16.f32 "
        "{%0,%1,%2,%3}, {%4,%5,%6,%7}, {%8,%9}, {%0,%1,%2,%3};"
        : "+f"(c[0]), "+f"(c[1]), "+f"(c[2]), "+f"(c[3])
        : "r"(a[0]), "r"(a[1]), "r"(a[2]), "r"(a[3]), "r"(b[0]), "r"(b[1]));
}

__device__ __forceinline__ void ldsm_x4(unsigned& r0, unsigned& r1, unsigned& r2, unsigned& r3,
                                        uint32_t addr) {
    asm volatile("ldmatrix.sync.aligned.m8n8.x4.shared.b16 {%0,%1,%2,%3}, [%4];"
                 : "=r"(r0), "=r"(r1), "=r"(r2), "=r"(r3) : "r"(addr));
}

__device__ __forceinline__ void cp16(unsigned int dst, const void* src, bool valid) {
    int sz = valid ? 16 : 0;
    asm volatile("cp.async.cg.shared.global [%0], [%1], 16, %2;"
                 :: "r"(dst), "l"(src), "r"(sz));
}
__device__ __forceinline__ void cp_commit() { asm volatile("cp.async.commit_group;" ::: "memory"); }
__device__ __forceinline__ void cp_wait1()  { asm volatile("cp.async.wait_group 1;" ::: "memory"); }

__device__ __forceinline__ float sigmoidf_fast(float v) { return 1.0f / (1.0f + __expf(-v)); }

__device__ __forceinline__ uint32_t smem_u32(const void* p) {
    uint32_t a;
    asm("{ .reg .u64 t; cvta.to.shared.u64 t, %1; cvt.u32.u64 %0, t; }" : "=r"(a) : "l"(p));
    return a;
}

__device__ __forceinline__ unsigned h2_bits(__half2 h) {
    unsigned u;
    *reinterpret_cast<__half2*>(&u) = h;
    return u;
}

// ---------------- fp16 pre-conversion passes ----------------------------------
__global__ __launch_bounds__(256) void cvt_x_kernel(const float* __restrict__ x, int total4) {
    for (int i = blockIdx.x * blockDim.x + threadIdx.x; i < total4; i += gridDim.x * blockDim.x) {
        const float4 v = __ldcs(reinterpret_cast<const float4*>(x) + i);
        uint2 o;
        o.x = h2_bits(__floats2half2_rn(v.x, v.y));
        o.y = h2_bits(__floats2half2_rn(v.z, v.w));
        reinterpret_cast<uint2*>(g_x16)[i] = o;
    }
}

// fp16 + transpose: g_w16t[z][n][k] = h(w_z[k][n])
__global__ __launch_bounds__(256) void cvt_wt_kernel(
    const float* __restrict__ w1, const float* __restrict__ w2, const float* __restrict__ w3) {
    __shared__ float tile[32][33];
    const int z = blockIdx.z;
    const float* __restrict__ w = (z == 0) ? w1 : ((z == 1) ? w2 : w3);
    const int n0 = blockIdx.x * 32;
    const int k0 = blockIdx.y * 32;
    const int tx = threadIdx.x & 31;
    const int ty = threadIdx.x >> 5;   // 0..7
#pragma unroll
    for (int i = 0; i < 32; i += 8)
        tile[ty + i][tx] = w[(size_t)(k0 + ty + i) * DF + n0 + tx];
    __syncthreads();
#pragma unroll
    for (int i = 0; i < 32; i += 8)
        g_w16t[(size_t)z * DF * DF + (size_t)(n0 + ty + i) * DF + k0 + tx] =
            __float2half_rn(tile[tx][ty + i]);
}

// ---------------- fused triple GEMM (fp16 m16n8k16 + ldmatrix) ----------------
// Block tile 128(M) x 128(N), K-tile 64, double-buffered dynamic smem (72KB).
// 256 threads = 8 warps (4 M x 2 N), warp tile 32x64 = 2x8 m16n8k16 fragments.
// grid.x = 12 combos (4 bn x 3 z) -> consecutive CTAs share the A tile in L2.
#define ROWB 144                        // bytes per smem row (72 halves, conflict-free)
#define TILE_BYTES (128 * ROWB)         // 18432
#define STAGE_BYTES (2 * TILE_BYTES)    // A + B
#define GEMM_SMEM (2 * STAGE_BYTES)     // 73728

__global__ __launch_bounds__(256, 2) void gemm3_kernel(
    const float* __restrict__ b2, const float* __restrict__ b3, int n)
{
    extern __shared__ __half smh[];
    const uint32_t smem_base = smem_u32(smh);

    const int combo = blockIdx.x;       // 0..11
    const int bn = (combo & 3) * 128;
    const int z  = combo >> 2;          // 0..2
    const int bm = blockIdx.y * 128;
    const __half* __restrict__ wz = g_w16t + (size_t)z * DF * DF;

    const int t    = threadIdx.x;
    const int lane = t & 31;
    const int warp = t >> 5;
    const int wm   = (warp & 3) * 32;
    const int wn   = (warp >> 2) * 64;
    const int gid  = lane >> 2;
    const int tig  = lane & 3;

    float acc[2][8][4];
#pragma unroll
    for (int mi = 0; mi < 2; mi++)
#pragma unroll
        for (int ni = 0; ni < 8; ni++)
#pragma unroll
            for (int r = 0; r < 4; r++) acc[mi][ni][r] = 0.0f;

    // ldmatrix per-lane address offsets (bytes, within a tile)
    const uint32_t aoff = (uint32_t)((wm + (lane & 15)) * ROWB + (lane >> 4) * 16);
    const uint32_t boff = (uint32_t)((wn + (lane & 7) + ((lane & 16) ? 8 : 0)) * ROWB
                                     + ((lane >> 3) & 1) * 16);

    const int NT = DF / 64;   // 8 k-tiles

    // fill: A 128x64 halves = 1024 16B-chunks (4/thread), same for B.
#define DO_PREFETCH(BF, K0)                                                          \
    {                                                                                \
        const uint32_t ab_ = smem_base + (BF) * STAGE_BYTES;                         \
        const uint32_t bb_ = ab_ + TILE_BYTES;                                       \
        _Pragma("unroll")                                                            \
        for (int i = 0; i < 4; i++) {                                                \
            const int idx = t + i * 256;                                             \
            const int r_  = idx >> 3;                                                \
            const int ch_ = idx & 7;                                                 \
            cp16(ab_ + r_ * ROWB + ch_ * 16,                                         \
                 g_x16 + (size_t)(bm + r_) * DF + (K0) + ch_ * 8, (bm + r_) < n);    \
        }                                                                            \
        _Pragma("unroll")                                                            \
        for (int i = 0; i < 4; i++) {                                                \
            const int idx = t + i * 256;                                             \
            const int r_  = idx >> 3;                                                \
            const int ch_ = idx & 7;                                                 \
            cp16(bb_ + r_ * ROWB + ch_ * 16,                                         \
                 wz + (size_t)(bn + r_) * DF + (K0) + ch_ * 8, true);                \
        }                                                                            \
    }

    int cb = 0;
    DO_PREFETCH(0, 0)
    cp_commit();

    for (int kt = 0; kt < NT; kt++) {
        if (kt + 1 < NT) DO_PREFETCH(cb ^ 1, (kt + 1) * 64)
        cp_commit();
        cp_wait1();
        __syncthreads();

        const uint32_t abase = smem_base + cb * STAGE_BYTES;
        const uint32_t bbase = abase + TILE_BYTES;

#pragma unroll
        for (int kk = 0; kk < 4; kk++) {           // 4 x k16 per tile
            const uint32_t kb = (uint32_t)(kk * 32);   // 16 halves = 32 bytes
            unsigned a[2][4];
#pragma unroll
            for (int mi = 0; mi < 2; mi++)
                ldsm_x4(a[mi][0], a[mi][1], a[mi][2], a[mi][3],
                        abase + aoff + mi * (16 * ROWB) + kb);
            unsigned b[8][2];
#pragma unroll
            for (int p = 0; p < 4; p++)
                ldsm_x4(b[2 * p][0], b[2 * p][1], b[2 * p + 1][0], b[2 * p + 1][1],
                        bbase + boff + p * (16 * ROWB) + kb);
#pragma unroll
            for (int mi = 0; mi < 2; mi++)
#pragma unroll
                for (int ni = 0; ni < 8; ni++)
                    mma_f16(acc[mi][ni], a[mi], b[ni]);
        }
        __syncthreads();
        cb ^= 1;
    }
#undef DO_PREFETCH

    // epilogue
    const float* __restrict__ bias = (z == 1) ? b2 : b3;

#pragma unroll
    for (int mi = 0; mi < 2; mi++) {
#pragma unroll
        for (int ni = 0; ni < 8; ni++) {
            const int col = bn + wn + ni * 8 + tig * 2;
            const int r0  = bm + wm + mi * 16 + gid;
            float v0 = acc[mi][ni][0], v1 = acc[mi][ni][1];
            float v2 = acc[mi][ni][2], v3 = acc[mi][ni][3];
            if (z >= 1) {
                const float bb0 = bias[col], bb1 = bias[col + 1];
                v0 += bb0; v1 += bb1; v2 += bb0; v3 += bb1;
            }
            if (z == 2) {
                v0 = sigmoidf_fast(v0); v1 = sigmoidf_fast(v1);
                v2 = sigmoidf_fast(v2); v3 = sigmoidf_fast(v3);
            }
            if (z == 1) {
                if (r0 < n)
                    *(float2*)(g_trans + (size_t)r0 * DF + col) = make_float2(v0, v1);
                if (r0 + 8 < n)
                    *(float2*)(g_trans + (size_t)(r0 + 8) * DF + col) = make_float2(v2, v3);
            } else {
                __half* __restrict__ outp = (z == 0) ? g_support_h : g_gate_h;
                if (r0 < n)
                    *(__half2*)(outp + (size_t)r0 * DF + col) = __floats2half2_rn(v0, v1);
                if (r0 + 8 < n)
                    *(__half2*)(outp + (size_t)(r0 + 8) * DF + col) = __floats2half2_rn(v2, v3);
            }
        }
    }
}

// ---------------- CSR build --------------------------------------------------
__global__ void zero_cnt_kernel(int n) {
    const int i = blockIdx.x * blockDim.x + threadIdx.x;
    if (i < n) g_row_cnt[i] = 0;
}

__global__ void hist_kernel(const int* __restrict__ er, int E) {
    for (int i = blockIdx.x * blockDim.x + threadIdx.x; i < E; i += gridDim.x * blockDim.x)
        atomicAdd(&g_row_cnt[__ldg(er + i)], 1);
}

__global__ __launch_bounds__(256) void scan_reduce_kernel(int n) {
    __shared__ int s[256];
    const int b = blockIdx.x, t = threadIdx.x;
    const int i0 = b * 512 + t;
    const int i1 = i0 + 256;
    int v = 0;
    if (i0 < n) v += g_row_cnt[i0];
    if (i1 < n) v += g_row_cnt[i1];
    s[t] = v;
    __syncthreads();
#pragma unroll
    for (int off = 128; off > 0; off >>= 1) {
        if (t < off) s[t] += s[t + off];
        __syncthreads();
    }
    if (t == 0) g_partials[b] = s[0];
}

__global__ __launch_bounds__(256) void scan_offsets_kernel(int nb) {
    __shared__ int s[256];
    const int t = threadIdx.x;
    const int v = (t < nb) ? g_partials[t] : 0;
    s[t] = v;
    __syncthreads();
#pragma unroll
    for (int off = 1; off < 256; off <<= 1) {
        const int u = (t >= off) ? s[t - off] : 0;
        __syncthreads();
        s[t] += u;
        __syncthreads();
    }
    if (t < nb) g_partials[t] = s[t] - v;   // exclusive
}

__global__ __launch_bounds__(256) void scan_fill_kernel(int n) {
    __shared__ int s[256];
    const int b = blockIdx.x, t = threadIdx.x;
    const int i0 = b * 512 + 2 * t;
    const int c0 = (i0 < n)     ? g_row_cnt[i0]     : 0;
    const int c1 = (i0 + 1 < n) ? g_row_cnt[i0 + 1] : 0;
    s[t] = c0 + c1;
    __syncthreads();
#pragma unroll
    for (int off = 1; off < 256; off <<= 1) {
        const int u = (t >= off) ? s[t - off] : 0;
        __syncthreads();
        s[t] += u;
        __syncthreads();
    }
    const int excl = s[t] - (c0 + c1) + g_partials[b];
    if (i0 < n)     { g_row_start[i0]     = excl;      g_row_cur[i0]     = excl; }
    if (i0 + 1 < n) { g_row_start[i0 + 1] = excl + c0; g_row_cur[i0 + 1] = excl + c0; }
}

__global__ void scatter_kernel(const int* __restrict__ er, const int* __restrict__ ec,
                               const float* __restrict__ ev, int E) {
    for (int i = blockIdx.x * blockDim.x + threadIdx.x; i < E; i += gridDim.x * blockDim.x) {
        const int r = __ldcs(er + i);
        const int p = atomicAdd(&g_row_cur[r], 1);
        g_edges[p] = make_int2(__ldcs(ec + i), __float_as_int(__ldcs(ev + i)));
    }
}

// ---------------- aggregation + fused final epilogue -------------------------
__device__ __forceinline__ void fma8_h(float acc[8], const uint4 raw, const float val) {
    const float2 f0 = __half22float2(*reinterpret_cast<const __half2*>(&raw.x));
    const float2 f1 = __half22float2(*reinterpret_cast<const __half2*>(&raw.y));
    const float2 f2 = __half22float2(*reinterpret_cast<const __half2*>(&raw.z));
    const float2 f3 = __half22float2(*reinterpret_cast<const __half2*>(&raw.w));
    acc[0] = fmaf(val, f0.x, acc[0]); acc[1] = fmaf(val, f0.y, acc[1]);
    acc[2] = fmaf(val, f1.x, acc[2]); acc[3] = fmaf(val, f1.y, acc[3]);
    acc[4] = fmaf(val, f2.x, acc[4]); acc[5] = fmaf(val, f2.y, acc[5]);
    acc[6] = fmaf(val, f3.x, acc[6]); acc[7] = fmaf(val, f3.y, acc[7]);
}

__global__ __launch_bounds__(64) void aggregate_kernel(
    const float* __restrict__ b1, float* __restrict__ out, int n)
{
    const int row = blockIdx.x;
    const int t   = threadIdx.x;
    const int c   = t << 3;

    const int start = g_row_start[row];
    const int deg   = g_row_cnt[row];

    float acc[8];
#pragma unroll
    for (int i = 0; i < 8; i++) acc[i] = 0.0f;

    __shared__ int2 se[64];

    for (int base = 0; base < deg; base += 64) {
        const int m = min(64, deg - base);
        if (t < m) se[t] = g_edges[start + base + t];
        __syncthreads();

        int i = 0;
        for (; i + 4 <= m; i += 4) {
            const int2 e0 = se[i], e1 = se[i + 1], e2 = se[i + 2], e3 = se[i + 3];
            const uint4 r0 = *reinterpret_cast<const uint4*>(g_support_h + (size_t)e0.x * DF + c);
            const uint4 r1 = *reinterpret_cast<const uint4*>(g_support_h + (size_t)e1.x * DF + c);
            const uint4 r2 = *reinterpret_cast<const uint4*>(g_support_h + (size_t)e2.x * DF + c);
            const uint4 r3 = *reinterpret_cast<const uint4*>(g_support_h + (size_t)e3.x * DF + c);
            fma8_h(acc, r0, __int_as_float(e0.y));
            fma8_h(acc, r1, __int_as_float(e1.y));
            fma8_h(acc, r2, __int_as_float(e2.y));
            fma8_h(acc, r3, __int_as_float(e3.y));
        }
        for (; i < m; i++) {
            const int2 e = se[i];
            const uint4 r = *reinterpret_cast<const uint4*>(g_support_h + (size_t)e.x * DF + c);
            fma8_h(acc, r, __int_as_float(e.y));
        }
        __syncthreads();
    }

    const size_t off = (size_t)row * DF + c;
    const float4 bb0 = *(const float4*)(b1 + c);
    const float4 bb1 = *(const float4*)(b1 + c + 4);
    const float4 tr0 = *(const float4*)(g_trans + off);
    const float4 tr1 = *(const float4*)(g_trans + off + 4);
    const uint4 graw = *(const uint4*)(g_gate_h + off);   // 8 halves
    const float2 g0 = __half22float2(*reinterpret_cast<const __half2*>(&graw.x));
    const float2 g1 = __half22float2(*reinterpret_cast<const __half2*>(&graw.y));
    const float2 g2 = __half22float2(*reinterpret_cast<const __half2*>(&graw.z));
    const float2 g3 = __half22float2(*reinterpret_cast<const __half2*>(&graw.w));

    float4 o0, o1;
    float r;
    r = fmaxf(acc[0] + bb0.x, 0.f);  o0.x = tr0.x + g0.x * (r - tr0.x);
    r = fmaxf(acc[1] + bb0.y, 0.f);  o0.y = tr0.y + g0.y * (r - tr0.y);
    r = fmaxf(acc[2] + bb0.z, 0.f);  o0.z = tr0.z + g1.x * (r - tr0.z);
    r = fmaxf(acc[3] + bb0.w, 0.f);  o0.w = tr0.w + g1.y * (r - tr0.w);
    r = fmaxf(acc[4] + bb1.x, 0.f);  o1.x = tr1.x + g2.x * (r - tr1.x);
    r = fmaxf(acc[5] + bb1.y, 0.f);  o1.y = tr1.y + g2.y * (r - tr1.y);
    r = fmaxf(acc[6] + bb1.z, 0.f);  o1.z = tr1.z + g3.x * (r - tr1.z);
    r = fmaxf(acc[7] + bb1.w, 0.f);  o1.w = tr1.w + g3.y * (r - tr1.w);
    __stcs((float4*)(out + off), o0);
    __stcs((float4*)(out + off + 4), o1);
}

// ---------------- launch ------------------------------------------------------
extern "C" void kernel_launch(void* const* d_in, const int* in_sizes, int n_in,
                              void* d_out, int out_size)
{
    const float* x  = (const float*)d_in[0];
    const float* w1 = (const float*)d_in[1];
    const float* w2 = (const float*)d_in[2];
    const float* w3 = (const float*)d_in[3];
    const float* b1 = (const float*)d_in[4];
    const float* b2 = (const float*)d_in[5];
    const float* b3 = (const float*)d_in[6];
    const int*   er = (const int*)d_in[7];
    const int*   ec = (const int*)d_in[8];
    const float* ev = (const float*)d_in[9];

    const int n = in_sizes[0] / DF;   // 100000
    const int E = in_sizes[7];        // 3200000
    float* out = (float*)d_out;

    static bool attr_set = false;
    if (!attr_set) {
        cudaFuncSetAttribute(gemm3_kernel, cudaFuncAttributeMaxDynamicSharedMemorySize, GEMM_SMEM);
        attr_set = true;
    }

    // ---- fork: CSR chain on side stream, runs concurrently with cvt+GEMM ----
    cudaEventRecord(g_evFork, 0);
    cudaStreamWaitEvent(g_s1, g_evFork, 0);

    zero_cnt_kernel<<<(n + 255) / 256, 256, 0, g_s1>>>(n);
    hist_kernel<<<2048, 256, 0, g_s1>>>(er, E);
    const int nb = (n + 511) / 512;   // <= 256
    scan_reduce_kernel<<<nb, 256, 0, g_s1>>>(n);
    scan_offsets_kernel<<<1, 256, 0, g_s1>>>(nb);
    scan_fill_kernel<<<nb, 256, 0, g_s1>>>(n);
    scatter_kernel<<<2048, 256, 0, g_s1>>>(er, ec, ev, E);
    cudaEventRecord(g_evJoin, g_s1);

    // ---- main stream: cvt + GEMM ----
    const int total4 = n * DF / 4;
    cvt_x_kernel<<<2048, 256>>>(x, total4);
    dim3 wtg(DF / 32, DF / 32, 3);
    cvt_wt_kernel<<<wtg, 256>>>(w1, w2, w3);

    dim3 ggrid(12, (n + 127) / 128, 1);
    gemm3_kernel<<<ggrid, 256, GEMM_SMEM>>>(b2, b3, n);

    // ---- join, then aggregate ----
    cudaStreamWaitEvent(0, g_evJoin, 0);
    aggregate_kernel<<<n, 64>>>(b1, out, n);
}